// round 16
// baseline (speedup 1.0000x reference)
#include <cuda_runtime.h>
#include <cuda_fp16.h>
#include <cstdint>

#define D 128
#define BM 128
#define PAD 136            // fp16 elems per SMEM row (272B = 68 words, 68%32=4 -> conflict-free)
#define BITS_WORDS 1568    // ceil(50000/32) rounded to int4 multiple
#define PRE_BLOCKS 65      // 65 blocks x 2 rows = 130 >= 129 (128 Wvo rows + c1 row)

// ---------------- device scratch (no allocations allowed) ----------------
// g_bits is statically zero-initialized; k_fix resets it every call, so the
// zero-at-entry invariant holds on all graph replays.
__device__ float g_c1[D];                        // b_v @ W_o + b_o
__device__ unsigned int g_bits[BITS_WORDS];      // indeg(v) > 0, 1 bit per node
__device__ __align__(16) unsigned short g_Bh[D * D];  // B[n][k] = W_vo[k][n], fp16

__device__ __forceinline__ unsigned short f16u(float x) {
    return __half_as_ushort(__float2half_rn(x));
}

// ---------------- kernel 1: fused prep (W_vo fp16 + c1) and indeg bitmap ----------------
// Blocks [0, PRE_BLOCKS): block b computes logical rows i = 2b + (tid>>7).
// Blocks [PRE_BLOCKS, ...): edge scatter as word-granular atomicOr (RED.OR) --
// byte stores RMW-serialize in LTS; bit reductions are the native path.
__global__ void k_pre(const float* __restrict__ Wv, const float* __restrict__ Wo,
                      const float* __restrict__ bv, const float* __restrict__ bo,
                      const int* __restrict__ ei, int E) {
    const int tid = threadIdx.x;
    const int b = blockIdx.x;
    if (b >= PRE_BLOCKS) {                        // ---- scatter portion ----
        int t = (b - PRE_BLOCKS) * 256 + tid;
        int E4 = E >> 2;
        if (t < E4) {
            int4 d = ((const int4*)(ei + E))[t];
            atomicOr(&g_bits[d.x >> 5], 1u << (d.x & 31));
            atomicOr(&g_bits[d.y >> 5], 1u << (d.y & 31));
            atomicOr(&g_bits[d.z >> 5], 1u << (d.z & 31));
            atomicOr(&g_bits[d.w >> 5], 1u << (d.w & 31));
        } else if (t == E4) {
            for (int e = E4 * 4; e < E; e++) {
                int v = ei[E + e];
                atomicOr(&g_bits[v >> 5], 1u << (v & 31));
            }
        }
        return;
    }
    // ---- prep portion ----
    __shared__ float vS[2][D];
    const int half = tid >> 7;                    // 0/1 -> logical row 2b+half
    const int j = tid & 127;                      // output column n
    const int i = 2 * b + half;
    vS[half][j] = (i < D) ? Wv[i * D + j] : ((i == D) ? bv[j] : 0.f);
    __syncthreads();

    const float* vrow = vS[half];
    float acc = 0.f;
    #pragma unroll 16
    for (int k = 0; k < D; k++)
        acc = fmaf(vrow[k], __ldg(Wo + k * D + j), acc);   // Wo coalesced, L2-hot

    if (i < D) {
        g_Bh[j * D + i] = f16u(acc);              // B[n=j][k=i]
    } else if (i == D) {
        g_c1[j] = acc + bo[j];
    }
}

// ---------------- kernel 2: HMMA GEMM (fp16 split, 2-term), 512 threads ----------------
// out[v,:] = node[v,:] @ W_vo + c1   (unconditional; zero-indeg rows fixed by k_fix)
// 16 warps/CTA: warp w -> row group rg=w>>1 (16 rows), n-half nh=w&1 (64 cols).
__global__ __launch_bounds__(512, 2)
void k_gemm_mma(const float* __restrict__ A, float* __restrict__ out, int V) {
    extern __shared__ __align__(16) unsigned short sm[];
    unsigned short* Ah = sm;                 // [128][PAD]
    unsigned short* Al = sm + BM * PAD;
    unsigned short* Bh = sm + 2 * BM * PAD;  // [128 n][PAD k]
    __shared__ float c1s[D];

    const int tid = threadIdx.x;
    const int wid = tid >> 5, lid = tid & 31;
    const int m0 = blockIdx.x * BM;

    // Stage B: 2048 uint4 (128 rows x 16 chunks) over 512 threads = 4 iters.
    #pragma unroll
    for (int i = 0; i < 4; i++) {
        int idx = tid + i * 512;
        int n = idx >> 4, c = idx & 15;
        *(uint4*)(Bh + n * PAD + c * 8) = ((const uint4*)g_Bh)[idx];
    }
    // Stage A: fp32 -> fp16 hi/lo. 4096 float4 over 512 threads = 8 iters.
    #pragma unroll
    for (int i = 0; i < 8; i++) {
        int idx = tid + i * 512;
        int row = idx >> 5, c4 = idx & 31;
        int gm = m0 + row;
        float4 v = make_float4(0.f, 0.f, 0.f, 0.f);
        if (gm < V) v = ((const float4*)A)[(size_t)gm * 32 + c4];
        __half h0 = __float2half_rn(v.x), h1 = __float2half_rn(v.y);
        __half h2 = __float2half_rn(v.z), h3 = __float2half_rn(v.w);
        uint2 hp = make_uint2((uint32_t)__half_as_ushort(h0) | ((uint32_t)__half_as_ushort(h1) << 16),
                              (uint32_t)__half_as_ushort(h2) | ((uint32_t)__half_as_ushort(h3) << 16));
        __half l0 = __float2half_rn(v.x - __half2float(h0));
        __half l1 = __float2half_rn(v.y - __half2float(h1));
        __half l2 = __float2half_rn(v.z - __half2float(h2));
        __half l3 = __float2half_rn(v.w - __half2float(h3));
        uint2 lp = make_uint2((uint32_t)__half_as_ushort(l0) | ((uint32_t)__half_as_ushort(l1) << 16),
                              (uint32_t)__half_as_ushort(l2) | ((uint32_t)__half_as_ushort(l3) << 16));
        *(uint2*)(Ah + row * PAD + c4 * 4) = hp;
        *(uint2*)(Al + row * PAD + c4 * 4) = lp;
    }
    if (tid < D) c1s[tid] = g_c1[tid];
    __syncthreads();

    // ---- MMA mainloop: warp = 16 rows x 64 cols; 8 kk x 8 n x 2 MMA ----
    const int rg = wid >> 1;                 // row group 0..7
    const int nh = wid & 1;                  // n half 0..1
    const int row0 = rg * 16;
    const int g = lid >> 2, t = lid & 3;
    float acc[8][4];
    #pragma unroll
    for (int n = 0; n < 8; n++) { acc[n][0] = acc[n][1] = acc[n][2] = acc[n][3] = 0.f; }

    const unsigned short* ah0 = Ah + (row0 + g) * PAD + 2 * t;
    const unsigned short* ah1 = Ah + (row0 + g + 8) * PAD + 2 * t;
    const unsigned short* al0 = Al + (row0 + g) * PAD + 2 * t;
    const unsigned short* al1 = Al + (row0 + g + 8) * PAD + 2 * t;
    const unsigned short* bhp = Bh + (nh * 64 + g) * PAD + 2 * t;

    #pragma unroll
    for (int kk = 0; kk < 8; kk++) {
        const int ko = kk * 16;
        uint32_t h0 = *(const uint32_t*)(ah0 + ko);
        uint32_t h1 = *(const uint32_t*)(ah1 + ko);
        uint32_t h2 = *(const uint32_t*)(ah0 + ko + 8);
        uint32_t h3 = *(const uint32_t*)(ah1 + ko + 8);
        uint32_t l0 = *(const uint32_t*)(al0 + ko);
        uint32_t l1 = *(const uint32_t*)(al1 + ko);
        uint32_t l2 = *(const uint32_t*)(al0 + ko + 8);
        uint32_t l3 = *(const uint32_t*)(al1 + ko + 8);
        #pragma unroll
        for (int n = 0; n < 8; n++) {
            uint32_t b0 = *(const uint32_t*)(bhp + n * 8 * PAD + ko);
            uint32_t b1 = *(const uint32_t*)(bhp + n * 8 * PAD + ko + 8);
            asm volatile(
                "mma.sync.aligned.m16n8k16.row.col.f32.f16.f16.f32 "
                "{%0,%1,%2,%3}, {%4,%5,%6,%7}, {%8,%9}, {%0,%1,%2,%3};"
                : "+f"(acc[n][0]), "+f"(acc[n][1]), "+f"(acc[n][2]), "+f"(acc[n][3])
                : "r"(h0), "r"(h1), "r"(h2), "r"(h3), "r"(b0), "r"(b1));
            asm volatile(
                "mma.sync.aligned.m16n8k16.row.col.f32.f16.f16.f32 "
                "{%0,%1,%2,%3}, {%4,%5,%6,%7}, {%8,%9}, {%0,%1,%2,%3};"
                : "+f"(acc[n][0]), "+f"(acc[n][1]), "+f"(acc[n][2]), "+f"(acc[n][3])
                : "r"(l0), "r"(l1), "r"(l2), "r"(l3), "r"(b0), "r"(b1));
        }
    }
    __syncthreads();   // done reading tiles; reuse smem as fp32 staging

    // ---- Epilogue: fragments -> SMEM (stride 132 floats), coalesced store ----
    float* Cst = (float*)sm;
    #pragma unroll
    for (int n = 0; n < 8; n++) {
        int c = nh * 64 + n * 8 + 2 * t;
        *(float2*)(Cst + (row0 + g) * 132 + c)     = make_float2(acc[n][0], acc[n][1]);
        *(float2*)(Cst + (row0 + g + 8) * 132 + c) = make_float2(acc[n][2], acc[n][3]);
    }
    __syncthreads();
    #pragma unroll
    for (int i = 0; i < 8; i++) {
        int idx = tid + i * 512;
        int row = idx >> 5, c4 = idx & 31;
        int gm = m0 + row;
        if (gm >= V) continue;
        float4 v = *(const float4*)(Cst + row * 132 + c4 * 4);
        float4 r;
        r.x = v.x + c1s[c4 * 4 + 0];
        r.y = v.y + c1s[c4 * 4 + 1];
        r.z = v.z + c1s[c4 * 4 + 2];
        r.w = v.w + c1s[c4 * 4 + 3];
        ((float4*)out)[(size_t)gm * 32 + c4] = r;
    }
}

// ---------------- kernel 3: fixup zero-indeg rows + bitmap self-reset ----------------
// Thread v: if bit clear -> out[v,:] = b_o (expected ~0 such nodes; Poisson(16)).
// Each 256-thread block owns exactly 8 bitmap words; resets them after use.
__global__ void k_fix(const float* __restrict__ bo, float* __restrict__ out, int V) {
    const int tid = threadIdx.x;
    const int v = blockIdx.x * 256 + tid;
    if (v < V) {
        unsigned int w = g_bits[v >> 5];
        if (!((w >> (v & 31)) & 1u)) {
            float4* orow = (float4*)(out + (size_t)v * D);
            const float4* b4 = (const float4*)bo;
            #pragma unroll
            for (int c = 0; c < 32; c++) orow[c] = b4[c];
        }
    }
    __syncthreads();                               // all reads of this block's words done
    if (tid < 2) {                                 // zero this block's 8 words (2 uint4)
        int w4 = blockIdx.x * 2 + tid;
        if (w4 < BITS_WORDS / 4) ((uint4*)g_bits)[w4] = make_uint4(0, 0, 0, 0);
    }
}

// ---------------- launch ----------------
extern "C" void kernel_launch(void* const* d_in, const int* in_sizes, int n_in,
                              void* d_out, int out_size) {
    const float* node = (const float*)d_in[0];
    const int*   ei   = (const int*)d_in[2];
    const float* Wv   = (const float*)d_in[7];
    const float* bv   = (const float*)d_in[8];
    const float* Wo   = (const float*)d_in[11];
    const float* bo   = (const float*)d_in[12];
    float* out = (float*)d_out;

    const int V = in_sizes[0] / D;
    const int E = in_sizes[2] / 2;

    const int scatter_blocks = (E / 4 + 256) / 256;
    k_pre<<<PRE_BLOCKS + scatter_blocks, 256>>>(Wv, Wo, bv, bo, ei, E);

    const int smem = 3 * BM * PAD * 2;   // 104448 B -> 2 CTAs/SM
    cudaFuncSetAttribute(k_gemm_mma, cudaFuncAttributeMaxDynamicSharedMemorySize, smem);
    k_gemm_mma<<<(V + BM - 1) / BM, 512, smem>>>(node, out, V);

    k_fix<<<(V + 255) / 256, 256>>>(bo, out, V);
}

// round 17
// speedup vs baseline: 2.2573x; 2.2573x over previous
#include <cuda_runtime.h>
#include <cuda_fp16.h>
#include <cstdint>

#define D 128
#define BM 128
#define PAD 136            // fp16 elems per SMEM row (272B = 68 words, 68%32=4 -> conflict-free)
#define BITS_WORDS 1568    // ceil(50000/32) rounded to int4 multiple
#define PRE_BLOCKS 65      // 65 blocks x 2 rows = 130 >= 129 (128 Wvo rows + c1 row)
#define SCAT_BLOCKS 128    // smem-bitmap scatter blocks

// ---------------- device scratch (no allocations allowed) ----------------
// g_bits is statically zero-initialized; k_fix resets it every call, so the
// zero-at-entry invariant holds on all graph replays.
__device__ float g_c1[D];                        // b_v @ W_o + b_o
__device__ unsigned int g_bits[BITS_WORDS];      // indeg(v) > 0, 1 bit per node
__device__ __align__(16) unsigned short g_Bh[D * D];  // B[n][k] = W_vo[k][n], fp16

__device__ __forceinline__ unsigned short f16u(float x) {
    return __half_as_ushort(__float2half_rn(x));
}

// ---------------- kernel 1: fused prep (W_vo fp16 + c1) and indeg bitmap ----------------
// Blocks [0, PRE_BLOCKS): block b computes logical rows i = 2b + (tid>>7).
// Blocks [PRE_BLOCKS, PRE_BLOCKS+SCAT_BLOCKS): per-block SMEM bitmap (random
// atomics stay on-chip; ATOMS spread ~2cyc/lane), then ONE coalesced word-level
// atomicOr sweep to merge. Global hot-spot atomics killed (R16: 800K global
// atomicOr onto 1568 words = 43.8us @ 1% issue).
__global__ void k_pre(const float* __restrict__ Wv, const float* __restrict__ Wo,
                      const float* __restrict__ bv, const float* __restrict__ bo,
                      const int* __restrict__ ei, int E) {
    const int tid = threadIdx.x;
    const int b = blockIdx.x;
    if (b >= PRE_BLOCKS) {                        // ---- scatter portion ----
        __shared__ unsigned int sb[BITS_WORDS];
        #pragma unroll
        for (int w = tid; w < BITS_WORDS; w += 256) sb[w] = 0u;
        __syncthreads();

        const int sb_id = b - PRE_BLOCKS;
        const int chunk = (E + SCAT_BLOCKS - 1) / SCAT_BLOCKS;
        const int start = sb_id * chunk;
        const int end = (start + chunk < E) ? (start + chunk) : E;
        for (int e = start + tid; e < end; e += 256) {
            int v = ei[E + e];                     // dest row, coalesced
            atomicOr(&sb[v >> 5], 1u << (v & 31)); // on-chip, no L2 round-trip
        }
        __syncthreads();

        for (int w = tid; w < BITS_WORDS; w += 256) {
            unsigned int m = sb[w];
            if (m) atomicOr(&g_bits[w], m);        // coalesced word-level merge
        }
        return;
    }
    // ---- prep portion ----
    __shared__ float vS[2][D];
    const int half = tid >> 7;                    // 0/1 -> logical row 2b+half
    const int j = tid & 127;                      // output column n
    const int i = 2 * b + half;
    vS[half][j] = (i < D) ? Wv[i * D + j] : ((i == D) ? bv[j] : 0.f);
    __syncthreads();

    const float* vrow = vS[half];
    float acc = 0.f;
    #pragma unroll 16
    for (int k = 0; k < D; k++)
        acc = fmaf(vrow[k], __ldg(Wo + k * D + j), acc);   // Wo coalesced, L2-hot

    if (i < D) {
        g_Bh[j * D + i] = f16u(acc);              // B[n=j][k=i]
    } else if (i == D) {
        g_c1[j] = acc + bo[j];
    }
}

// ---------------- kernel 2: HMMA GEMM (fp16 split, 2-term), 512 threads ----------------
// out[v,:] = node[v,:] @ W_vo + c1   (unconditional; zero-indeg rows fixed by k_fix)
// 16 warps/CTA: warp w -> row group rg=w>>1 (16 rows), n-half nh=w&1 (64 cols).
__global__ __launch_bounds__(512, 2)
void k_gemm_mma(const float* __restrict__ A, float* __restrict__ out, int V) {
    extern __shared__ __align__(16) unsigned short sm[];
    unsigned short* Ah = sm;                 // [128][PAD]
    unsigned short* Al = sm + BM * PAD;
    unsigned short* Bh = sm + 2 * BM * PAD;  // [128 n][PAD k]
    __shared__ float c1s[D];

    const int tid = threadIdx.x;
    const int wid = tid >> 5, lid = tid & 31;
    const int m0 = blockIdx.x * BM;

    // Stage B: 2048 uint4 (128 rows x 16 chunks) over 512 threads = 4 iters.
    #pragma unroll
    for (int i = 0; i < 4; i++) {
        int idx = tid + i * 512;
        int n = idx >> 4, c = idx & 15;
        *(uint4*)(Bh + n * PAD + c * 8) = ((const uint4*)g_Bh)[idx];
    }
    // Stage A: fp32 -> fp16 hi/lo. 4096 float4 over 512 threads = 8 iters.
    #pragma unroll
    for (int i = 0; i < 8; i++) {
        int idx = tid + i * 512;
        int row = idx >> 5, c4 = idx & 31;
        int gm = m0 + row;
        float4 v = make_float4(0.f, 0.f, 0.f, 0.f);
        if (gm < V) v = ((const float4*)A)[(size_t)gm * 32 + c4];
        __half h0 = __float2half_rn(v.x), h1 = __float2half_rn(v.y);
        __half h2 = __float2half_rn(v.z), h3 = __float2half_rn(v.w);
        uint2 hp = make_uint2((uint32_t)__half_as_ushort(h0) | ((uint32_t)__half_as_ushort(h1) << 16),
                              (uint32_t)__half_as_ushort(h2) | ((uint32_t)__half_as_ushort(h3) << 16));
        __half l0 = __float2half_rn(v.x - __half2float(h0));
        __half l1 = __float2half_rn(v.y - __half2float(h1));
        __half l2 = __float2half_rn(v.z - __half2float(h2));
        __half l3 = __float2half_rn(v.w - __half2float(h3));
        uint2 lp = make_uint2((uint32_t)__half_as_ushort(l0) | ((uint32_t)__half_as_ushort(l1) << 16),
                              (uint32_t)__half_as_ushort(l2) | ((uint32_t)__half_as_ushort(l3) << 16));
        *(uint2*)(Ah + row * PAD + c4 * 4) = hp;
        *(uint2*)(Al + row * PAD + c4 * 4) = lp;
    }
    if (tid < D) c1s[tid] = g_c1[tid];
    __syncthreads();

    // ---- MMA mainloop: warp = 16 rows x 64 cols; 8 kk x 8 n x 2 MMA ----
    const int rg = wid >> 1;                 // row group 0..7
    const int nh = wid & 1;                  // n half 0..1
    const int row0 = rg * 16;
    const int g = lid >> 2, t = lid & 3;
    float acc[8][4];
    #pragma unroll
    for (int n = 0; n < 8; n++) { acc[n][0] = acc[n][1] = acc[n][2] = acc[n][3] = 0.f; }

    const unsigned short* ah0 = Ah + (row0 + g) * PAD + 2 * t;
    const unsigned short* ah1 = Ah + (row0 + g + 8) * PAD + 2 * t;
    const unsigned short* al0 = Al + (row0 + g) * PAD + 2 * t;
    const unsigned short* al1 = Al + (row0 + g + 8) * PAD + 2 * t;
    const unsigned short* bhp = Bh + (nh * 64 + g) * PAD + 2 * t;

    #pragma unroll
    for (int kk = 0; kk < 8; kk++) {
        const int ko = kk * 16;
        uint32_t h0 = *(const uint32_t*)(ah0 + ko);
        uint32_t h1 = *(const uint32_t*)(ah1 + ko);
        uint32_t h2 = *(const uint32_t*)(ah0 + ko + 8);
        uint32_t h3 = *(const uint32_t*)(ah1 + ko + 8);
        uint32_t l0 = *(const uint32_t*)(al0 + ko);
        uint32_t l1 = *(const uint32_t*)(al1 + ko);
        uint32_t l2 = *(const uint32_t*)(al0 + ko + 8);
        uint32_t l3 = *(const uint32_t*)(al1 + ko + 8);
        #pragma unroll
        for (int n = 0; n < 8; n++) {
            uint32_t b0 = *(const uint32_t*)(bhp + n * 8 * PAD + ko);
            uint32_t b1 = *(const uint32_t*)(bhp + n * 8 * PAD + ko + 8);
            asm volatile(
                "mma.sync.aligned.m16n8k16.row.col.f32.f16.f16.f32 "
                "{%0,%1,%2,%3}, {%4,%5,%6,%7}, {%8,%9}, {%0,%1,%2,%3};"
                : "+f"(acc[n][0]), "+f"(acc[n][1]), "+f"(acc[n][2]), "+f"(acc[n][3])
                : "r"(h0), "r"(h1), "r"(h2), "r"(h3), "r"(b0), "r"(b1));
            asm volatile(
                "mma.sync.aligned.m16n8k16.row.col.f32.f16.f16.f32 "
                "{%0,%1,%2,%3}, {%4,%5,%6,%7}, {%8,%9}, {%0,%1,%2,%3};"
                : "+f"(acc[n][0]), "+f"(acc[n][1]), "+f"(acc[n][2]), "+f"(acc[n][3])
                : "r"(l0), "r"(l1), "r"(l2), "r"(l3), "r"(b0), "r"(b1));
        }
    }
    __syncthreads();   // done reading tiles; reuse smem as fp32 staging

    // ---- Epilogue: fragments -> SMEM (stride 132 floats), coalesced store ----
    float* Cst = (float*)sm;
    #pragma unroll
    for (int n = 0; n < 8; n++) {
        int c = nh * 64 + n * 8 + 2 * t;
        *(float2*)(Cst + (row0 + g) * 132 + c)     = make_float2(acc[n][0], acc[n][1]);
        *(float2*)(Cst + (row0 + g + 8) * 132 + c) = make_float2(acc[n][2], acc[n][3]);
    }
    __syncthreads();
    #pragma unroll
    for (int i = 0; i < 8; i++) {
        int idx = tid + i * 512;
        int row = idx >> 5, c4 = idx & 31;
        int gm = m0 + row;
        if (gm >= V) continue;
        float4 v = *(const float4*)(Cst + row * 132 + c4 * 4);
        float4 r;
        r.x = v.x + c1s[c4 * 4 + 0];
        r.y = v.y + c1s[c4 * 4 + 1];
        r.z = v.z + c1s[c4 * 4 + 2];
        r.w = v.w + c1s[c4 * 4 + 3];
        ((float4*)out)[(size_t)gm * 32 + c4] = r;
    }
}

// ---------------- kernel 3: fixup zero-indeg rows + bitmap self-reset ----------------
// Thread v: if bit clear -> out[v,:] = b_o (expected ~0 such nodes; Poisson(16)).
// Each 256-thread block owns exactly 8 bitmap words; resets them after use.
__global__ void k_fix(const float* __restrict__ bo, float* __restrict__ out, int V) {
    const int tid = threadIdx.x;
    const int v = blockIdx.x * 256 + tid;
    if (v < V) {
        unsigned int w = g_bits[v >> 5];
        if (!((w >> (v & 31)) & 1u)) {
            float4* orow = (float4*)(out + (size_t)v * D);
            const float4* b4 = (const float4*)bo;
            #pragma unroll
            for (int c = 0; c < 32; c++) orow[c] = b4[c];
        }
    }
    __syncthreads();                               // all reads of this block's words done
    if (tid < 2) {                                 // zero this block's 8 words (2 uint4)
        int w4 = blockIdx.x * 2 + tid;
        if (w4 < BITS_WORDS / 4) ((uint4*)g_bits)[w4] = make_uint4(0, 0, 0, 0);
    }
}

// ---------------- launch ----------------
extern "C" void kernel_launch(void* const* d_in, const int* in_sizes, int n_in,
                              void* d_out, int out_size) {
    const float* node = (const float*)d_in[0];
    const int*   ei   = (const int*)d_in[2];
    const float* Wv   = (const float*)d_in[7];
    const float* bv   = (const float*)d_in[8];
    const float* Wo   = (const float*)d_in[11];
    const float* bo   = (const float*)d_in[12];
    float* out = (float*)d_out;

    const int V = in_sizes[0] / D;
    const int E = in_sizes[2] / 2;

    k_pre<<<PRE_BLOCKS + SCAT_BLOCKS, 256>>>(Wv, Wo, bv, bo, ei, E);

    const int smem = 3 * BM * PAD * 2;   // 104448 B -> 2 CTAs/SM
    cudaFuncSetAttribute(k_gemm_mma, cudaFuncAttributeMaxDynamicSharedMemorySize, smem);
    k_gemm_mma<<<(V + BM - 1) / BM, 512, smem>>>(node, out, V);

    k_fix<<<(V + 255) / 256, 256>>>(bo, out, V);
}